// round 14
// baseline (speedup 1.0000x reference)
#include <cuda_runtime.h>
#include <math.h>
#include <stdint.h>

// ---------------- problem constants ----------------
#define NPAIRS_MAX 200000
#define MAX_NB 6
#define NWARPS 8
#define THREADS (NWARPS * 32)
#define MLP_BLOCKS 148
#define PI_F 3.14159265358979323846f

#define FEAT1 300              // dense1 streamed rows (atype block handled directly)
#define XROWS 328              // padded rows; each row is a float4 (4 pair slots)

// shared offsets (floats); W1/W2/W3 stored INTERLEAVED:
//   sm[i*64 + 2*o] = W[i][o], sm[i*64 + 2*o + 1] = W[i][o+32]  (o in 0..31)
#define OFF_W1   0
#define OFF_W2   20608
#define OFF_W3   24704
#define OFF_WO   28800
#define OFF_B1   28864
#define OFF_G1   28928
#define OFF_BE1  28992
#define OFF_B2   29056
#define OFF_G2   29120
#define OFF_BE2  29184
#define OFF_B3   29248
#define OFF_G3   29312
#define OFF_BE3  29376
#define OFF_BO   29440
#define OFF_X    29444                              // 16B aligned
#define SMEM_FLOATS (OFF_X + NWARPS * XROWS * 4)    // 39940
#define SMEM_BYTES  (SMEM_FLOATS * 4)               // 159760 -> 1 block/SM

// ---------------- device globals ----------------
__device__ int    g_count;
__device__ int    g_done;
__device__ double g_sum;
__device__ int    g_p0[NPAIRS_MAX];
__device__ int    g_p1[NPAIRS_MAX];
__device__ float4 g_rec[NPAIRS_MAX];   // rij.x, rij.y, rij.z, w

__constant__ float c_zidx[10] = {1.f, 3.f, 5.f, 6.f, 7.f, 8.f, 9.f, 11.f, 15.f, 16.f};

// ---------------- helpers ----------------
__device__ __forceinline__ void box_inverse(const float* b, float* bi) {
    float det = b[0] * (b[4] * b[8] - b[5] * b[7])
              - b[1] * (b[3] * b[8] - b[5] * b[6])
              + b[2] * (b[3] * b[7] - b[4] * b[6]);
    float id = 1.f / det;
    bi[0] = (b[4] * b[8] - b[5] * b[7]) * id;
    bi[1] = (b[2] * b[7] - b[1] * b[8]) * id;
    bi[2] = (b[1] * b[5] - b[2] * b[4]) * id;
    bi[3] = (b[5] * b[6] - b[3] * b[8]) * id;
    bi[4] = (b[0] * b[8] - b[2] * b[6]) * id;
    bi[5] = (b[2] * b[3] - b[0] * b[5]) * id;
    bi[6] = (b[3] * b[7] - b[4] * b[6]) * id;
    bi[7] = (b[1] * b[6] - b[0] * b[7]) * id;
    bi[8] = (b[0] * b[4] - b[1] * b[3]) * id;
}

__device__ __forceinline__ float3 pbc3(float dx, float dy, float dz,
                                       const float* B, const float* Bi) {
    float s0 = dx * Bi[0] + dy * Bi[3] + dz * Bi[6];
    float s1 = dx * Bi[1] + dy * Bi[4] + dz * Bi[7];
    float s2 = dx * Bi[2] + dy * Bi[5] + dz * Bi[8];
    s0 -= floorf(s0 + 0.5f);
    s1 -= floorf(s1 + 0.5f);
    s2 -= floorf(s2 + 0.5f);
    float3 r;
    r.x = s0 * B[0] + s1 * B[3] + s2 * B[6];
    r.y = s0 * B[1] + s1 * B[4] + s2 * B[7];
    r.z = s0 * B[2] + s1 * B[5] + s2 * B[8];
    return r;
}

__device__ __forceinline__ float4 allreduce4(float4 v) {
#pragma unroll
    for (int o = 16; o > 0; o >>= 1) {
        v.x += __shfl_xor_sync(0xffffffffu, v.x, o);
        v.y += __shfl_xor_sync(0xffffffffu, v.y, o);
        v.z += __shfl_xor_sync(0xffffffffu, v.z, o);
        v.w += __shfl_xor_sync(0xffffffffu, v.w, o);
    }
    return v;
}

__device__ __forceinline__ void fma4(float4& a, const float4& x, float w) {
    a.x = fmaf(x.x, w, a.x); a.y = fmaf(x.y, w, a.y);
    a.z = fmaf(x.z, w, a.z); a.w = fmaf(x.w, w, a.w);
}
__device__ __forceinline__ float4 add4(const float4& a, const float4& b) {
    return make_float4(a.x + b.x, a.y + b.y, a.z + b.z, a.w + b.w);
}

// 4 pair-slots per warp: scalar-FMA dense, interleaved weights (1 LDS.64/row),
// software-pipelined 4-row blocks, even/odd split accumulators.
// ext0/ext1: extra contribution (dense1's atype block), zero otherwise.
__device__ __forceinline__ void dense4i(
    const float* __restrict__ Wi, const float* __restrict__ bb,
    const float* __restrict__ gg, const float* __restrict__ be,
    float* x, int inDim, int lane, float4 ext0, float4 ext1)
{
    float b0 = bb[lane], b1 = bb[lane + 32];
    float4 a0e = make_float4(b0, b0, b0, b0);
    float4 a1e = make_float4(b1, b1, b1, b1);
    float4 a0o = ext0;           // fold ext into the odd chain start
    float4 a1o = ext1;
    const float2* wp = (const float2*)Wi + lane;
#pragma unroll 2
    for (int i = 0; i < inDim; i += 4) {
        float4 xv0 = *(const float4*)(x + i * 4);
        float4 xv1 = *(const float4*)(x + (i + 1) * 4);
        float4 xv2 = *(const float4*)(x + (i + 2) * 4);
        float4 xv3 = *(const float4*)(x + (i + 3) * 4);
        float2 w0 = wp[i * 32];
        float2 w1 = wp[(i + 1) * 32];
        float2 w2 = wp[(i + 2) * 32];
        float2 w3 = wp[(i + 3) * 32];
        fma4(a0e, xv0, w0.x); fma4(a1e, xv0, w0.y);
        fma4(a0o, xv1, w1.x); fma4(a1o, xv1, w1.y);
        fma4(a0e, xv2, w2.x); fma4(a1e, xv2, w2.y);
        fma4(a0o, xv3, w3.x); fma4(a1o, xv3, w3.y);
    }
    float4 a0 = add4(a0e, a0o);
    float4 a1 = add4(a1e, a1o);

    float4 s = add4(a0, a1);
    s = allreduce4(s);
    float4 mu = make_float4(s.x * (1.f/64.f), s.y * (1.f/64.f), s.z * (1.f/64.f), s.w * (1.f/64.f));
    float4 d0 = make_float4(a0.x - mu.x, a0.y - mu.y, a0.z - mu.z, a0.w - mu.w);
    float4 d1 = make_float4(a1.x - mu.x, a1.y - mu.y, a1.z - mu.z, a1.w - mu.w);
    float4 v = make_float4(d0.x*d0.x + d1.x*d1.x, d0.y*d0.y + d1.y*d1.y,
                           d0.z*d0.z + d1.z*d1.z, d0.w*d0.w + d1.w*d1.w);
    v = allreduce4(v);
    float4 r = make_float4(rsqrtf(v.x * (1.f/64.f) + 1e-6f),
                           rsqrtf(v.y * (1.f/64.f) + 1e-6f),
                           rsqrtf(v.z * (1.f/64.f) + 1e-6f),
                           rsqrtf(v.w * (1.f/64.f) + 1e-6f));
    float g0 = gg[lane], g1 = gg[lane + 32];
    float e0 = be[lane], e1 = be[lane + 32];
    float4 y0 = make_float4(fmaxf(d0.x * r.x * g0 + e0, 0.f),
                            fmaxf(d0.y * r.y * g0 + e0, 0.f),
                            fmaxf(d0.z * r.z * g0 + e0, 0.f),
                            fmaxf(d0.w * r.w * g0 + e0, 0.f));
    float4 y1 = make_float4(fmaxf(d1.x * r.x * g1 + e1, 0.f),
                            fmaxf(d1.y * r.y * g1 + e1, 0.f),
                            fmaxf(d1.z * r.z * g1 + e1, 0.f),
                            fmaxf(d1.w * r.w * g1 + e1, 0.f));
    __syncwarp();
    *(float4*)(x + lane * 4) = y0;
    *(float4*)(x + (lane + 32) * 4) = y1;
    __syncwarp();
}

// ---------------- kernel 1: filter + compact ----------------
__global__ void k_filter(const float* __restrict__ pos,
                         const float* __restrict__ box,
                         const float* __restrict__ valid,
                         const int* __restrict__ pairs,
                         const int* __restrict__ molid,
                         int npairs)
{
    int i = blockIdx.x * blockDim.x + threadIdx.x;
    if (i >= npairs) return;
    int p0 = pairs[3 * i];
    int p1 = pairs[3 * i + 1];
    if (p1 - p0 <= 0) { p0 -= 1; p1 -= 2; }
    if (p0 >= p1) return;
    if (__ldg(molid + p0) == __ldg(molid + p1)) return;
    float bs = __ldg(valid + i);
    if (bs == 0.f) return;

    float B[9], Bi[9];
#pragma unroll
    for (int k = 0; k < 9; k++) B[k] = box[k];
    box_inverse(B, Bi);

    float ax = __ldg(pos + 3 * p0), ay = __ldg(pos + 3 * p0 + 1), az = __ldg(pos + 3 * p0 + 2);
    float bx = __ldg(pos + 3 * p1), by = __ldg(pos + 3 * p1 + 1), bz = __ldg(pos + 3 * p1 + 2);
    float3 r = pbc3(bx - ax, by - ay, bz - az, B, Bi);
    float cx = r.x + 1e-10f, cy = r.y + 1e-10f, cz = r.z + 1e-10f;
    float dn = sqrtf(cx * cx + cy * cy + cz * cz);
    if (dn > 5.0f) return;
    float cut = 0.5f * (1.f + __cosf(PI_F * dn * (1.f / 5.f)));
    float w = bs * cut;
    if (w <= 0.f) return;

    int slot = atomicAdd(&g_count, 1);
    g_p0[slot] = p0;
    g_p1[slot] = p1;
    g_rec[slot] = make_float4(r.x, r.y, r.z, w);
}

// ---------------- kernel 2: features + MLP, 4 pairs per warp ----------------
__global__ __launch_bounds__(THREADS, 1)
void k_mlp(const float* __restrict__ pos,
           const float* __restrict__ box,
           const int* __restrict__ topo,
           const int* __restrict__ atype,
           const float* __restrict__ W1, const float* __restrict__ b1,
           const float* __restrict__ g1, const float* __restrict__ be1,
           const float* __restrict__ W2, const float* __restrict__ b2,
           const float* __restrict__ g2, const float* __restrict__ be2,
           const float* __restrict__ W3, const float* __restrict__ b3,
           const float* __restrict__ g3, const float* __restrict__ be3,
           const float* __restrict__ Wo, const float* __restrict__ bo,
           float* __restrict__ out)
{
    extern __shared__ float sm[];
    __shared__ double s_part[NWARPS];
    int tid = threadIdx.x;

    // stage weights INTERLEAVED: sm[i*64 + 2*o] = W[i][o], sm[i*64 + 2*o+1] = W[i][o+32]
    for (int idx = tid; idx < 20608; idx += THREADS) {
        int i = idx >> 6, o = idx & 63;
        int p = (o < 32) ? (o * 2) : ((o - 32) * 2 + 1);
        sm[OFF_W1 + (i << 6) + p] = __ldg(W1 + idx);
    }
    for (int idx = tid; idx < 4096; idx += THREADS) {
        int i = idx >> 6, o = idx & 63;
        int p = (o < 32) ? (o * 2) : ((o - 32) * 2 + 1);
        sm[OFF_W2 + (i << 6) + p] = __ldg(W2 + idx);
        sm[OFF_W3 + (i << 6) + p] = __ldg(W3 + idx);
    }
    if (tid < 64) {
        sm[OFF_WO + tid] = Wo[tid];
        sm[OFF_B1 + tid] = b1[tid]; sm[OFF_G1 + tid] = g1[tid]; sm[OFF_BE1 + tid] = be1[tid];
        sm[OFF_B2 + tid] = b2[tid]; sm[OFF_G2 + tid] = g2[tid]; sm[OFF_BE2 + tid] = be2[tid];
        sm[OFF_B3 + tid] = b3[tid]; sm[OFF_G3 + tid] = g3[tid]; sm[OFF_BE3 + tid] = be3[tid];
    }
    if (tid == 0) sm[OFF_BO] = bo[0];
    __syncthreads();

    float B[9], Bi[9];
#pragma unroll
    for (int k = 0; k < 9; k++) B[k] = box[k];
    box_inverse(B, Bi);

    int lane = tid & 31;
    int wid = tid >> 5;
    float* x = sm + OFF_X + wid * (XROWS * 4);
    int n = g_count;
    int ngroups = (n + 3) >> 2;

    float mu_acsf = (float)lane * (5.f / 19.f);              // lanes 0..19
    float mu_apsf = -1.f + (float)(lane - 20) * (2.f / 9.f); // lanes 20..29
    double wacc = 0.0;

    for (int grp = wid * gridDim.x + blockIdx.x; grp < ngroups;
         grp += gridDim.x * NWARPS) {
        int base = grp * 4;
        int np = n - base; if (np > 4) np = 4;

        int p0s[4], p1s[4];
        float uxs[4], uys[4], uzs[4], ws[4];
#pragma unroll
        for (int s = 0; s < 4; s++) {
            if (s < np) {
                p0s[s] = g_p0[base + s];
                p1s[s] = g_p1[base + s];
                float4 rc = g_rec[base + s];
                float cx = rc.x + 1e-10f, cy = rc.y + 1e-10f, cz = rc.z + 1e-10f;
                float r2 = cx * cx + cy * cy + cz * cz;
                float ui = rsqrtf(r2);
                float dn = r2 * ui;
                ui = 1.f / (dn + 1e-10f);
                uxs[s] = rc.x * ui; uys[s] = rc.y * ui; uzs[s] = rc.z * ui;
                ws[s] = rc.w;
            } else { p0s[s] = 0; p1s[s] = 0; uxs[s] = uys[s] = uzs[s] = 0.f; ws[s] = 0.f; }
        }

        // zero streamed feature rows (0..299, pad to 304)
        {
            float4 z = make_float4(0.f, 0.f, 0.f, 0.f);
            float4* xv = (float4*)x;
            for (int i = lane; i < 304; i += 32) xv[i] = z;
        }
        __syncwarp();

        // parallel gather: lanes 0..23 fetch neighbors for slots {0,1} (A) / {2,3} (B);
        // lanes 24..31 fetch the 8 pair-atom centers.
        int nbA = -1, tA = 0, nbB = -1, tB = 0;
        float xA = 0.f, yA = 0.f, zA = 0.f, xB = 0.f, yB = 0.f, zB = 0.f;
        float cpx = 0.f, cpy = 0.f, cpz = 0.f; int cpt = 0;
        if (lane < 24) {
            int pr = lane / 12;
            int e = lane % 12;
            int side = e / 6, m = e % 6;
            if (pr < np) {
                int a = side ? p1s[pr] : p0s[pr];
                nbA = __ldg(topo + a * MAX_NB + m);
            }
            int prB = pr + 2;
            if (prB < np) {
                int a = side ? p1s[prB] : p0s[prB];
                nbB = __ldg(topo + a * MAX_NB + m);
            }
        } else {
            int k = lane - 24;
            int slot = k >> 1, which = k & 1;
            if (slot < np) {
                int a = which ? p1s[slot] : p0s[slot];
                cpx = __ldg(pos + 3 * a); cpy = __ldg(pos + 3 * a + 1); cpz = __ldg(pos + 3 * a + 2);
                cpt = __ldg(atype + a);
            }
        }
        if (lane < 24) {
            if (nbA >= 0) { xA = __ldg(pos + 3 * nbA); yA = __ldg(pos + 3 * nbA + 1); zA = __ldg(pos + 3 * nbA + 2); tA = __ldg(atype + nbA); }
            if (nbB >= 0) { xB = __ldg(pos + 3 * nbB); yB = __ldg(pos + 3 * nbB + 1); zB = __ldg(pos + 3 * nbB + 2); tB = __ldg(atype + nbB); }
        }
        __syncwarp();

        // pair-atom types for the direct dense1 atype contribution
        int t0s[4], t1s[4];
#pragma unroll
        for (int s = 0; s < 4; s++) {
            t0s[s] = __shfl_sync(0xffffffffu, cpt, 24 + s * 2);
            t1s[s] = __shfl_sync(0xffffffffu, cpt, 25 + s * 2);
        }

        // contribution loop: 4 slots x 12 edges, batched by 4 with hoisted
        // shuffles + predicated math (independent chains -> ILP)
#pragma unroll
        for (int slot = 0; slot < 4; slot++) {
            if (slot >= np) break;
            float c0x = __shfl_sync(0xffffffffu, cpx, 24 + slot * 2);
            float c0y = __shfl_sync(0xffffffffu, cpy, 24 + slot * 2);
            float c0z = __shfl_sync(0xffffffffu, cpz, 24 + slot * 2);
            float c1x = __shfl_sync(0xffffffffu, cpx, 25 + slot * 2);
            float c1y = __shfl_sync(0xffffffffu, cpy, 25 + slot * 2);
            float c1z = __shfl_sync(0xffffffffu, cpz, 25 + slot * 2);
            float ux = uxs[slot], uy = uys[slot], uz = uzs[slot];
            float cw = ws[slot];
            int q0 = p0s[slot], q1 = p1s[slot];

#pragma unroll
            for (int b = 0; b < 3; b++) {
                // hoist all shuffles for 4 edges
                int nb4[4], te4[4];
                float ex4[4], ey4[4], ez4[4];
#pragma unroll
                for (int j = 0; j < 4; j++) {
                    int srcLane = (slot & 1) * 12 + b * 4 + j;
                    if (slot < 2) {
                        nb4[j] = __shfl_sync(0xffffffffu, nbA, srcLane);
                        ex4[j] = __shfl_sync(0xffffffffu, xA, srcLane);
                        ey4[j] = __shfl_sync(0xffffffffu, yA, srcLane);
                        ez4[j] = __shfl_sync(0xffffffffu, zA, srcLane);
                        te4[j] = __shfl_sync(0xffffffffu, tA, srcLane);
                    } else {
                        nb4[j] = __shfl_sync(0xffffffffu, nbB, srcLane);
                        ex4[j] = __shfl_sync(0xffffffffu, xB, srcLane);
                        ey4[j] = __shfl_sync(0xffffffffu, yB, srcLane);
                        ez4[j] = __shfl_sync(0xffffffffu, zB, srcLane);
                        te4[j] = __shfl_sync(0xffffffffu, tB, srcLane);
                    }
                }
                // 4 independent predicated chains
#pragma unroll
                for (int j = 0; j < 4; j++) {
                    bool valid = (nb4[j] >= 0);
                    int e = b * 4 + j;
                    int side = e / 6;
                    float cx = side ? c1x : c0x;
                    float cy = side ? c1y : c0y;
                    float cz = side ? c1z : c0z;
                    float3 d = pbc3(ex4[j] - cx, ey4[j] - cy, ez4[j] - cz, B, Bi);
                    float ddx = d.x + 1e-10f, ddy = d.y + 1e-10f, ddz = d.z + 1e-10f;
                    float r2 = ddx * ddx + ddy * ddy + ddz * ddz;
                    float rinv = rsqrtf(r2);
                    float edn = r2 * rinv;

                    if (lane < 20) {
                        float fx = edn * 0.2f;
                        if (valid && fx < 1.f) {
                            float fc = 0.5f * (__cosf(PI_F * fx) + 1.f);
                            float dm = edn - mu_acsf;
                            x[(lane * 10 + te4[j]) * 4 + slot] += 0.5f * fc * __expf(-100.f * dm * dm);
                        }
                    } else if (lane < 30) {
                        if (valid && nb4[j] != q0 && nb4[j] != q1) {
                            float sgn = side ? -1.f : 1.f;
                            float cg = (d.x * ux + d.y * uy + d.z * uz) * rinv * sgn;
                            float dm = cg - mu_apsf;
                            x[(200 + (lane - 20) * 10 + te4[j]) * 4 + slot] +=
                                0.5f * cw * __expf(-25.f * dm * dm);
                        }
                    }
                }
            }
        }
        __syncwarp();

        // direct atype-block contribution for dense1 (rows 300..321):
        // row300 = Zj, row 301+t0 = 1, row 311 = Zk, row 312+t1 = 1
        float4 ext0, ext1;
        {
            const float2* wp = (const float2*)(sm + OFF_W1) + lane;
            float2 wzj = wp[300 * 32];
            float2 wzk = wp[311 * 32];
#pragma unroll
            for (int s = 0; s < 4; s++) {
                float2 wo0 = wp[(301 + t0s[s]) * 32];
                float2 wo1 = wp[(312 + t1s[s]) * 32];
                float zj = c_zidx[t0s[s]];
                float zk = c_zidx[t1s[s]];
                (&ext0.x)[s] = fmaf(zj, wzj.x, wo0.x) + fmaf(zk, wzk.x, wo1.x);
                (&ext1.x)[s] = fmaf(zj, wzj.y, wo0.y) + fmaf(zk, wzk.y, wo1.y);
            }
        }

        dense4i(sm + OFF_W1, sm + OFF_B1, sm + OFF_G1, sm + OFF_BE1, x, FEAT1, lane, ext0, ext1);
        {
            float4 z4 = make_float4(0.f, 0.f, 0.f, 0.f);
            dense4i(sm + OFF_W2, sm + OFF_B2, sm + OFF_G2, sm + OFF_BE2, x, 64, lane, z4, z4);
            dense4i(sm + OFF_W3, sm + OFF_B3, sm + OFF_G3, sm + OFF_BE3, x, 64, lane, z4, z4);
        }

        float wo0 = sm[OFF_WO + lane], wo1 = sm[OFF_WO + lane + 32];
        float4 xv0 = *(const float4*)(x + lane * 4);
        float4 xv1 = *(const float4*)(x + (lane + 32) * 4);
        float4 v = make_float4(xv0.x * wo0 + xv1.x * wo1,
                               xv0.y * wo0 + xv1.y * wo1,
                               xv0.z * wo0 + xv1.z * wo1,
                               xv0.w * wo0 + xv1.w * wo1);
        v = allreduce4(v);
        if (lane == 0) {
            float bov = sm[OFF_BO];
            wacc += (double)((v.x + bov) * ws[0] + (v.y + bov) * ws[1]
                           + (v.z + bov) * ws[2] + (v.w + bov) * ws[3]);
        }
    }

    // finalize: block-reduce -> one global atomic; last block writes output
    if (lane == 0) s_part[wid] = wacc;
    __syncthreads();
    if (tid == 0) {
        double t = 0.0;
#pragma unroll
        for (int i = 0; i < NWARPS; i++) t += s_part[i];
        atomicAdd(&g_sum, t);
        __threadfence();
        int done = atomicAdd(&g_done, 1);
        if (done == (int)gridDim.x - 1) {
            double s = atomicAdd(&g_sum, 0.0);   // coherent read
            out[0] = (float)s;
            g_sum = 0.0;
            g_count = 0;
            g_done = 0;
        }
    }
}

// ---------------- launch ----------------
extern "C" void kernel_launch(void* const* d_in, const int* in_sizes, int n_in,
                              void* d_out, int out_size)
{
    const float* pos   = (const float*)d_in[0];
    const float* box   = (const float*)d_in[1];
    const float* valid = (const float*)d_in[2];
    const float* W1 = (const float*)d_in[3];
    const float* b1 = (const float*)d_in[4];
    const float* g1 = (const float*)d_in[5];
    const float* be1 = (const float*)d_in[6];
    const float* W2 = (const float*)d_in[7];
    const float* b2 = (const float*)d_in[8];
    const float* g2 = (const float*)d_in[9];
    const float* be2 = (const float*)d_in[10];
    const float* W3 = (const float*)d_in[11];
    const float* b3 = (const float*)d_in[12];
    const float* g3 = (const float*)d_in[13];
    const float* be3 = (const float*)d_in[14];
    const float* Wo = (const float*)d_in[15];
    const float* bo = (const float*)d_in[16];
    const int* pairs = (const int*)d_in[17];
    const int* topo  = (const int*)d_in[18];
    // d_in[19] topo_mask: redundant with topo != -1
    const int* molid = (const int*)d_in[20];
    const int* atype = (const int*)d_in[21];

    int npairs = in_sizes[17] / 3;
    if (npairs > NPAIRS_MAX) npairs = NPAIRS_MAX;

    cudaFuncSetAttribute(k_mlp, cudaFuncAttributeMaxDynamicSharedMemorySize, SMEM_BYTES);

    k_filter<<<(npairs + 255) / 256, 256>>>(pos, box, valid, pairs, molid, npairs);
    k_mlp<<<MLP_BLOCKS, THREADS, SMEM_BYTES>>>(pos, box, topo, atype,
        W1, b1, g1, be1, W2, b2, g2, be2, W3, b3, g3, be3, Wo, bo,
        (float*)d_out);
}

// round 15
// speedup vs baseline: 1.1081x; 1.1081x over previous
#include <cuda_runtime.h>
#include <math.h>
#include <stdint.h>

// ---------------- problem constants ----------------
#define NPAIRS_MAX 200000
#define MAX_NB 6
#define NWARPS 8
#define THREADS (NWARPS * 32)
#define MLP_BLOCKS 148
#define PI_F 3.14159265358979323846f

#define FEAT1 300              // dense1 streamed rows (atype block folded directly)
#define XROWS 328              // padded rows; each row is a float4 (4 pair slots)

// shared offsets (floats); weights ROW-MAJOR (R12 layout — the fast path)
#define OFF_W1   0
#define OFF_W2   20608
#define OFF_W3   24704
#define OFF_WO   28800
#define OFF_B1   28864
#define OFF_G1   28928
#define OFF_BE1  28992
#define OFF_B2   29056
#define OFF_G2   29120
#define OFF_BE2  29184
#define OFF_B3   29248
#define OFF_G3   29312
#define OFF_BE3  29376
#define OFF_BO   29440
#define OFF_X    29444                              // 16B aligned
#define SMEM_FLOATS (OFF_X + NWARPS * XROWS * 4)    // 39940
#define SMEM_BYTES  (SMEM_FLOATS * 4)               // 159760 -> 1 block/SM

// ---------------- device globals ----------------
__device__ int    g_count;
__device__ int    g_done;
__device__ double g_sum;
__device__ int    g_p0[NPAIRS_MAX];
__device__ int    g_p1[NPAIRS_MAX];
__device__ float4 g_rec[NPAIRS_MAX];   // rij.x, rij.y, rij.z, w

__constant__ float c_zidx[10] = {1.f, 3.f, 5.f, 6.f, 7.f, 8.f, 9.f, 11.f, 15.f, 16.f};

// ---------------- helpers ----------------
__device__ __forceinline__ void box_inverse(const float* b, float* bi) {
    float det = b[0] * (b[4] * b[8] - b[5] * b[7])
              - b[1] * (b[3] * b[8] - b[5] * b[6])
              + b[2] * (b[3] * b[7] - b[4] * b[6]);
    float id = 1.f / det;
    bi[0] = (b[4] * b[8] - b[5] * b[7]) * id;
    bi[1] = (b[2] * b[7] - b[1] * b[8]) * id;
    bi[2] = (b[1] * b[5] - b[2] * b[4]) * id;
    bi[3] = (b[5] * b[6] - b[3] * b[8]) * id;
    bi[4] = (b[0] * b[8] - b[2] * b[6]) * id;
    bi[5] = (b[2] * b[3] - b[0] * b[5]) * id;
    bi[6] = (b[3] * b[7] - b[4] * b[6]) * id;
    bi[7] = (b[1] * b[6] - b[0] * b[7]) * id;
    bi[8] = (b[0] * b[4] - b[1] * b[3]) * id;
}

__device__ __forceinline__ float3 pbc3(float dx, float dy, float dz,
                                       const float* B, const float* Bi) {
    float s0 = dx * Bi[0] + dy * Bi[3] + dz * Bi[6];
    float s1 = dx * Bi[1] + dy * Bi[4] + dz * Bi[7];
    float s2 = dx * Bi[2] + dy * Bi[5] + dz * Bi[8];
    s0 -= floorf(s0 + 0.5f);
    s1 -= floorf(s1 + 0.5f);
    s2 -= floorf(s2 + 0.5f);
    float3 r;
    r.x = s0 * B[0] + s1 * B[3] + s2 * B[6];
    r.y = s0 * B[1] + s1 * B[4] + s2 * B[7];
    r.z = s0 * B[2] + s1 * B[5] + s2 * B[8];
    return r;
}

__device__ __forceinline__ float4 allreduce4(float4 v) {
#pragma unroll
    for (int o = 16; o > 0; o >>= 1) {
        v.x += __shfl_xor_sync(0xffffffffu, v.x, o);
        v.y += __shfl_xor_sync(0xffffffffu, v.y, o);
        v.z += __shfl_xor_sync(0xffffffffu, v.z, o);
        v.w += __shfl_xor_sync(0xffffffffu, v.w, o);
    }
    return v;
}

__device__ __forceinline__ void fma4(float4& a, const float4& x, float w) {
    a.x = fmaf(x.x, w, a.x); a.y = fmaf(x.y, w, a.y);
    a.z = fmaf(x.z, w, a.z); a.w = fmaf(x.w, w, a.w);
}
__device__ __forceinline__ float4 add4(const float4& a, const float4& b) {
    return make_float4(a.x + b.x, a.y + b.y, a.z + b.z, a.w + b.w);
}

// 4 pair-slots per warp, R12's software-pipelined dense (row-major weights,
// scalar LDS.32 weight loads, 4-row blocks, split even/odd accumulators).
// ext0/ext1: extra contribution (dense1's atype block), zero otherwise —
// folded into the odd-chain accumulator seed.
__device__ __forceinline__ void dense4(
    const float* __restrict__ Ws, const float* __restrict__ bb,
    const float* __restrict__ gg, const float* __restrict__ be,
    float* x, int inDim, int lane, float4 ext0, float4 ext1)
{
    float b0 = bb[lane], b1 = bb[lane + 32];
    float4 a0e = make_float4(b0, b0, b0, b0);
    float4 a1e = make_float4(b1, b1, b1, b1);
    float4 a0o = ext0;
    float4 a1o = ext1;
    const float* w0p = Ws + lane;
    const float* w1p = Ws + lane + 32;
#pragma unroll 2
    for (int i = 0; i < inDim; i += 4) {
        float4 xv0 = *(const float4*)(x + i * 4);
        float4 xv1 = *(const float4*)(x + (i + 1) * 4);
        float4 xv2 = *(const float4*)(x + (i + 2) * 4);
        float4 xv3 = *(const float4*)(x + (i + 3) * 4);
        float w00 = w0p[i * 64],       w10 = w1p[i * 64];
        float w01 = w0p[(i + 1) * 64], w11 = w1p[(i + 1) * 64];
        float w02 = w0p[(i + 2) * 64], w12 = w1p[(i + 2) * 64];
        float w03 = w0p[(i + 3) * 64], w13 = w1p[(i + 3) * 64];
        fma4(a0e, xv0, w00); fma4(a1e, xv0, w10);
        fma4(a0o, xv1, w01); fma4(a1o, xv1, w11);
        fma4(a0e, xv2, w02); fma4(a1e, xv2, w12);
        fma4(a0o, xv3, w03); fma4(a1o, xv3, w13);
    }
    float4 a0 = add4(a0e, a0o);
    float4 a1 = add4(a1e, a1o);

    float4 s = add4(a0, a1);
    s = allreduce4(s);
    float4 mu = make_float4(s.x * (1.f/64.f), s.y * (1.f/64.f), s.z * (1.f/64.f), s.w * (1.f/64.f));
    float4 d0 = make_float4(a0.x - mu.x, a0.y - mu.y, a0.z - mu.z, a0.w - mu.w);
    float4 d1 = make_float4(a1.x - mu.x, a1.y - mu.y, a1.z - mu.z, a1.w - mu.w);
    float4 v = make_float4(d0.x*d0.x + d1.x*d1.x, d0.y*d0.y + d1.y*d1.y,
                           d0.z*d0.z + d1.z*d1.z, d0.w*d0.w + d1.w*d1.w);
    v = allreduce4(v);
    float4 r = make_float4(rsqrtf(v.x * (1.f/64.f) + 1e-6f),
                           rsqrtf(v.y * (1.f/64.f) + 1e-6f),
                           rsqrtf(v.z * (1.f/64.f) + 1e-6f),
                           rsqrtf(v.w * (1.f/64.f) + 1e-6f));
    float g0 = gg[lane], g1 = gg[lane + 32];
    float e0 = be[lane], e1 = be[lane + 32];
    float4 y0 = make_float4(fmaxf(d0.x * r.x * g0 + e0, 0.f),
                            fmaxf(d0.y * r.y * g0 + e0, 0.f),
                            fmaxf(d0.z * r.z * g0 + e0, 0.f),
                            fmaxf(d0.w * r.w * g0 + e0, 0.f));
    float4 y1 = make_float4(fmaxf(d1.x * r.x * g1 + e1, 0.f),
                            fmaxf(d1.y * r.y * g1 + e1, 0.f),
                            fmaxf(d1.z * r.z * g1 + e1, 0.f),
                            fmaxf(d1.w * r.w * g1 + e1, 0.f));
    __syncwarp();
    *(float4*)(x + lane * 4) = y0;
    *(float4*)(x + (lane + 32) * 4) = y1;
    __syncwarp();
}

// ---------------- kernel 1: filter + compact ----------------
__global__ void k_filter(const float* __restrict__ pos,
                         const float* __restrict__ box,
                         const float* __restrict__ valid,
                         const int* __restrict__ pairs,
                         const int* __restrict__ molid,
                         int npairs)
{
    int i = blockIdx.x * blockDim.x + threadIdx.x;
    if (i >= npairs) return;
    int p0 = pairs[3 * i];
    int p1 = pairs[3 * i + 1];
    if (p1 - p0 <= 0) { p0 -= 1; p1 -= 2; }
    if (p0 >= p1) return;
    if (__ldg(molid + p0) == __ldg(molid + p1)) return;
    float bs = __ldg(valid + i);
    if (bs == 0.f) return;

    float B[9], Bi[9];
#pragma unroll
    for (int k = 0; k < 9; k++) B[k] = box[k];
    box_inverse(B, Bi);

    float ax = __ldg(pos + 3 * p0), ay = __ldg(pos + 3 * p0 + 1), az = __ldg(pos + 3 * p0 + 2);
    float bx = __ldg(pos + 3 * p1), by = __ldg(pos + 3 * p1 + 1), bz = __ldg(pos + 3 * p1 + 2);
    float3 r = pbc3(bx - ax, by - ay, bz - az, B, Bi);
    float cx = r.x + 1e-10f, cy = r.y + 1e-10f, cz = r.z + 1e-10f;
    float dn = sqrtf(cx * cx + cy * cy + cz * cz);
    if (dn > 5.0f) return;
    float cut = 0.5f * (1.f + __cosf(PI_F * dn * (1.f / 5.f)));
    float w = bs * cut;
    if (w <= 0.f) return;

    int slot = atomicAdd(&g_count, 1);
    g_p0[slot] = p0;
    g_p1[slot] = p1;
    g_rec[slot] = make_float4(r.x, r.y, r.z, w);
}

// ---------------- kernel 2: features + MLP, 4 pairs per warp ----------------
__global__ __launch_bounds__(THREADS, 1)
void k_mlp(const float* __restrict__ pos,
           const float* __restrict__ box,
           const int* __restrict__ topo,
           const int* __restrict__ atype,
           const float* __restrict__ W1, const float* __restrict__ b1,
           const float* __restrict__ g1, const float* __restrict__ be1,
           const float* __restrict__ W2, const float* __restrict__ b2,
           const float* __restrict__ g2, const float* __restrict__ be2,
           const float* __restrict__ W3, const float* __restrict__ b3,
           const float* __restrict__ g3, const float* __restrict__ be3,
           const float* __restrict__ Wo, const float* __restrict__ bo,
           float* __restrict__ out)
{
    extern __shared__ float sm[];
    __shared__ double s_part[NWARPS];
    int tid = threadIdx.x;

    // stage weights (straight row-major float4 copies — R12 layout)
    {
        const float4* W1v = (const float4*)W1;
        float4* s1 = (float4*)(sm + OFF_W1);
        for (int i = tid; i < 20608 / 4; i += THREADS) s1[i] = W1v[i];
        const float4* W2v = (const float4*)W2;
        const float4* W3v = (const float4*)W3;
        float4* s2 = (float4*)(sm + OFF_W2);
        float4* s3 = (float4*)(sm + OFF_W3);
        for (int i = tid; i < 1024; i += THREADS) { s2[i] = W2v[i]; s3[i] = W3v[i]; }
        if (tid < 64) {
            sm[OFF_WO + tid] = Wo[tid];
            sm[OFF_B1 + tid] = b1[tid]; sm[OFF_G1 + tid] = g1[tid]; sm[OFF_BE1 + tid] = be1[tid];
            sm[OFF_B2 + tid] = b2[tid]; sm[OFF_G2 + tid] = g2[tid]; sm[OFF_BE2 + tid] = be2[tid];
            sm[OFF_B3 + tid] = b3[tid]; sm[OFF_G3 + tid] = g3[tid]; sm[OFF_BE3 + tid] = be3[tid];
        }
        if (tid == 0) sm[OFF_BO] = bo[0];
    }
    __syncthreads();

    float B[9], Bi[9];
#pragma unroll
    for (int k = 0; k < 9; k++) B[k] = box[k];
    box_inverse(B, Bi);

    int lane = tid & 31;
    int wid = tid >> 5;
    float* x = sm + OFF_X + wid * (XROWS * 4);
    int n = g_count;
    int ngroups = (n + 3) >> 2;

    float mu_acsf = (float)lane * (5.f / 19.f);              // lanes 0..19
    float mu_apsf = -1.f + (float)(lane - 20) * (2.f / 9.f); // lanes 20..29
    double wacc = 0.0;

    for (int grp = wid * gridDim.x + blockIdx.x; grp < ngroups;
         grp += gridDim.x * NWARPS) {
        int base = grp * 4;
        int np = n - base; if (np > 4) np = 4;

        int p0s[4], p1s[4];
        float uxs[4], uys[4], uzs[4], ws[4];
#pragma unroll
        for (int s = 0; s < 4; s++) {
            if (s < np) {
                p0s[s] = g_p0[base + s];
                p1s[s] = g_p1[base + s];
                float4 rc = g_rec[base + s];
                float cx = rc.x + 1e-10f, cy = rc.y + 1e-10f, cz = rc.z + 1e-10f;
                float r2 = cx * cx + cy * cy + cz * cz;
                float ui = rsqrtf(r2);
                float dn = r2 * ui;
                ui = 1.f / (dn + 1e-10f);
                uxs[s] = rc.x * ui; uys[s] = rc.y * ui; uzs[s] = rc.z * ui;
                ws[s] = rc.w;
            } else { p0s[s] = 0; p1s[s] = 0; uxs[s] = uys[s] = uzs[s] = 0.f; ws[s] = 0.f; }
        }

        // zero streamed feature rows (0..299, pad to 304)
        {
            float4 z = make_float4(0.f, 0.f, 0.f, 0.f);
            float4* xv = (float4*)x;
            for (int i = lane; i < 304; i += 32) xv[i] = z;
        }
        __syncwarp();

        // parallel gather: lanes 0..23 fetch neighbors for slots {0,1} (A) / {2,3} (B);
        // lanes 24..31 fetch the 8 pair-atom centers.
        int nbA = -1, tA = 0, nbB = -1, tB = 0;
        float xA = 0.f, yA = 0.f, zA = 0.f, xB = 0.f, yB = 0.f, zB = 0.f;
        float cpx = 0.f, cpy = 0.f, cpz = 0.f; int cpt = 0;
        if (lane < 24) {
            int pr = lane / 12;
            int e = lane % 12;
            int side = e / 6, m = e % 6;
            if (pr < np) {
                int a = side ? p1s[pr] : p0s[pr];
                nbA = __ldg(topo + a * MAX_NB + m);
            }
            int prB = pr + 2;
            if (prB < np) {
                int a = side ? p1s[prB] : p0s[prB];
                nbB = __ldg(topo + a * MAX_NB + m);
            }
        } else {
            int k = lane - 24;
            int slot = k >> 1, which = k & 1;
            if (slot < np) {
                int a = which ? p1s[slot] : p0s[slot];
                cpx = __ldg(pos + 3 * a); cpy = __ldg(pos + 3 * a + 1); cpz = __ldg(pos + 3 * a + 2);
                cpt = __ldg(atype + a);
            }
        }
        if (lane < 24) {
            if (nbA >= 0) { xA = __ldg(pos + 3 * nbA); yA = __ldg(pos + 3 * nbA + 1); zA = __ldg(pos + 3 * nbA + 2); tA = __ldg(atype + nbA); }
            if (nbB >= 0) { xB = __ldg(pos + 3 * nbB); yB = __ldg(pos + 3 * nbB + 1); zB = __ldg(pos + 3 * nbB + 2); tB = __ldg(atype + nbB); }
        }
        __syncwarp();

        // pair-atom types for the direct dense1 atype contribution
        int t0s[4], t1s[4];
#pragma unroll
        for (int s = 0; s < 4; s++) {
            t0s[s] = __shfl_sync(0xffffffffu, cpt, 24 + s * 2);
            t1s[s] = __shfl_sync(0xffffffffu, cpt, 25 + s * 2);
        }

        // contribution loop: 4 slots x 12 edges, batched by 4 with hoisted
        // shuffles + predicated math (independent chains -> ILP)
#pragma unroll
        for (int slot = 0; slot < 4; slot++) {
            if (slot >= np) break;
            float c0x = __shfl_sync(0xffffffffu, cpx, 24 + slot * 2);
            float c0y = __shfl_sync(0xffffffffu, cpy, 24 + slot * 2);
            float c0z = __shfl_sync(0xffffffffu, cpz, 24 + slot * 2);
            float c1x = __shfl_sync(0xffffffffu, cpx, 25 + slot * 2);
            float c1y = __shfl_sync(0xffffffffu, cpy, 25 + slot * 2);
            float c1z = __shfl_sync(0xffffffffu, cpz, 25 + slot * 2);
            float ux = uxs[slot], uy = uys[slot], uz = uzs[slot];
            float cw = ws[slot];
            int q0 = p0s[slot], q1 = p1s[slot];

#pragma unroll
            for (int b = 0; b < 3; b++) {
                // hoist all shuffles for 4 edges
                int nb4[4], te4[4];
                float ex4[4], ey4[4], ez4[4];
#pragma unroll
                for (int j = 0; j < 4; j++) {
                    int srcLane = (slot & 1) * 12 + b * 4 + j;
                    if (slot < 2) {
                        nb4[j] = __shfl_sync(0xffffffffu, nbA, srcLane);
                        ex4[j] = __shfl_sync(0xffffffffu, xA, srcLane);
                        ey4[j] = __shfl_sync(0xffffffffu, yA, srcLane);
                        ez4[j] = __shfl_sync(0xffffffffu, zA, srcLane);
                        te4[j] = __shfl_sync(0xffffffffu, tA, srcLane);
                    } else {
                        nb4[j] = __shfl_sync(0xffffffffu, nbB, srcLane);
                        ex4[j] = __shfl_sync(0xffffffffu, xB, srcLane);
                        ey4[j] = __shfl_sync(0xffffffffu, yB, srcLane);
                        ez4[j] = __shfl_sync(0xffffffffu, zB, srcLane);
                        te4[j] = __shfl_sync(0xffffffffu, tB, srcLane);
                    }
                }
                // 4 independent predicated chains
#pragma unroll
                for (int j = 0; j < 4; j++) {
                    bool valid = (nb4[j] >= 0);
                    int e = b * 4 + j;
                    int side = e / 6;
                    float cx = side ? c1x : c0x;
                    float cy = side ? c1y : c0y;
                    float cz = side ? c1z : c0z;
                    float3 d = pbc3(ex4[j] - cx, ey4[j] - cy, ez4[j] - cz, B, Bi);
                    float ddx = d.x + 1e-10f, ddy = d.y + 1e-10f, ddz = d.z + 1e-10f;
                    float r2 = ddx * ddx + ddy * ddy + ddz * ddz;
                    float rinv = rsqrtf(r2);
                    float edn = r2 * rinv;

                    if (lane < 20) {
                        float fx = edn * 0.2f;
                        if (valid && fx < 1.f) {
                            float fc = 0.5f * (__cosf(PI_F * fx) + 1.f);
                            float dm = edn - mu_acsf;
                            x[(lane * 10 + te4[j]) * 4 + slot] += 0.5f * fc * __expf(-100.f * dm * dm);
                        }
                    } else if (lane < 30) {
                        if (valid && nb4[j] != q0 && nb4[j] != q1) {
                            float sgn = side ? -1.f : 1.f;
                            float cg = (d.x * ux + d.y * uy + d.z * uz) * rinv * sgn;
                            float dm = cg - mu_apsf;
                            x[(200 + (lane - 20) * 10 + te4[j]) * 4 + slot] +=
                                0.5f * cw * __expf(-25.f * dm * dm);
                        }
                    }
                }
            }
        }
        __syncwarp();

        // direct atype-block contribution for dense1 (rows 300..321):
        // row 300 = Zj, row 301+t0 = 1, row 311 = Zk, row 312+t1 = 1
        float4 ext0, ext1;
        {
            const float* Ws = sm + OFF_W1;
            float wzj0 = Ws[300 * 64 + lane], wzj1 = Ws[300 * 64 + lane + 32];
            float wzk0 = Ws[311 * 64 + lane], wzk1 = Ws[311 * 64 + lane + 32];
#pragma unroll
            for (int s = 0; s < 4; s++) {
                float wo00 = Ws[(301 + t0s[s]) * 64 + lane];
                float wo01 = Ws[(301 + t0s[s]) * 64 + lane + 32];
                float wo10 = Ws[(312 + t1s[s]) * 64 + lane];
                float wo11 = Ws[(312 + t1s[s]) * 64 + lane + 32];
                float zj = c_zidx[t0s[s]];
                float zk = c_zidx[t1s[s]];
                (&ext0.x)[s] = fmaf(zj, wzj0, wo00) + fmaf(zk, wzk0, wo10);
                (&ext1.x)[s] = fmaf(zj, wzj1, wo01) + fmaf(zk, wzk1, wo11);
            }
        }

        dense4(sm + OFF_W1, sm + OFF_B1, sm + OFF_G1, sm + OFF_BE1, x, FEAT1, lane, ext0, ext1);
        {
            float4 z4 = make_float4(0.f, 0.f, 0.f, 0.f);
            dense4(sm + OFF_W2, sm + OFF_B2, sm + OFF_G2, sm + OFF_BE2, x, 64, lane, z4, z4);
            dense4(sm + OFF_W3, sm + OFF_B3, sm + OFF_G3, sm + OFF_BE3, x, 64, lane, z4, z4);
        }

        float wo0 = sm[OFF_WO + lane], wo1 = sm[OFF_WO + lane + 32];
        float4 xv0 = *(const float4*)(x + lane * 4);
        float4 xv1 = *(const float4*)(x + (lane + 32) * 4);
        float4 v = make_float4(xv0.x * wo0 + xv1.x * wo1,
                               xv0.y * wo0 + xv1.y * wo1,
                               xv0.z * wo0 + xv1.z * wo1,
                               xv0.w * wo0 + xv1.w * wo1);
        v = allreduce4(v);
        if (lane == 0) {
            float bov = sm[OFF_BO];
            wacc += (double)((v.x + bov) * ws[0] + (v.y + bov) * ws[1]
                           + (v.z + bov) * ws[2] + (v.w + bov) * ws[3]);
        }
    }

    // finalize: block-reduce -> one global atomic; last block writes output
    if (lane == 0) s_part[wid] = wacc;
    __syncthreads();
    if (tid == 0) {
        double t = 0.0;
#pragma unroll
        for (int i = 0; i < NWARPS; i++) t += s_part[i];
        atomicAdd(&g_sum, t);
        __threadfence();
        int done = atomicAdd(&g_done, 1);
        if (done == (int)gridDim.x - 1) {
            double s = atomicAdd(&g_sum, 0.0);   // coherent read
            out[0] = (float)s;
            g_sum = 0.0;
            g_count = 0;
            g_done = 0;
        }
    }
}

// ---------------- launch ----------------
extern "C" void kernel_launch(void* const* d_in, const int* in_sizes, int n_in,
                              void* d_out, int out_size)
{
    const float* pos   = (const float*)d_in[0];
    const float* box   = (const float*)d_in[1];
    const float* valid = (const float*)d_in[2];
    const float* W1 = (const float*)d_in[3];
    const float* b1 = (const float*)d_in[4];
    const float* g1 = (const float*)d_in[5];
    const float* be1 = (const float*)d_in[6];
    const float* W2 = (const float*)d_in[7];
    const float* b2 = (const float*)d_in[8];
    const float* g2 = (const float*)d_in[9];
    const float* be2 = (const float*)d_in[10];
    const float* W3 = (const float*)d_in[11];
    const float* b3 = (const float*)d_in[12];
    const float* g3 = (const float*)d_in[13];
    const float* be3 = (const float*)d_in[14];
    const float* Wo = (const float*)d_in[15];
    const float* bo = (const float*)d_in[16];
    const int* pairs = (const int*)d_in[17];
    const int* topo  = (const int*)d_in[18];
    // d_in[19] topo_mask: redundant with topo != -1
    const int* molid = (const int*)d_in[20];
    const int* atype = (const int*)d_in[21];

    int npairs = in_sizes[17] / 3;
    if (npairs > NPAIRS_MAX) npairs = NPAIRS_MAX;

    cudaFuncSetAttribute(k_mlp, cudaFuncAttributeMaxDynamicSharedMemorySize, SMEM_BYTES);

    k_filter<<<(npairs + 255) / 256, 256>>>(pos, box, valid, pairs, molid, npairs);
    k_mlp<<<MLP_BLOCKS, THREADS, SMEM_BYTES>>>(pos, box, topo, atype,
        W1, b1, g1, be1, W2, b2, g2, be2, W3, b3, g3, be3, Wo, bo,
        (float*)d_out);
}